// round 16
// baseline (speedup 1.0000x reference)
#include <cuda_runtime.h>
#include <math.h>
#include <float.h>

#define TT 256
#define BB 32
#define CC 64
#define BEAM 16
#define TOPK 4
#define NEGV (-1e9f)

typedef unsigned long long u64;

__device__ float g_lp[TT * BB * CC];

__device__ __forceinline__ float laexp(float a, float b) {
    return fmaxf(a, b) + log1pf(expf(-fabsf(a - b)));
}
__device__ __forceinline__ unsigned f2ord(float v) {
    unsigned u = __float_as_uint(v);
    return u ^ (unsigned)(((int)u >> 31) | 0x80000000);
}
__device__ __forceinline__ float ord2f(unsigned o) {
    unsigned u = (o & 0x80000000u) ? (o ^ 0x80000000u) : ~o;
    return __uint_as_float(u);
}

// ---------------------------------------------------------------------------
__global__ void logsoftmax_kernel(const float* __restrict__ data) {
    int row  = blockIdx.x * 8 + (threadIdx.x >> 5);
    int lane = threadIdx.x & 31;
    if (row >= TT * BB) return;
    const float* x = data + row * CC;
    float v0 = x[lane], v1 = x[lane + 32];
    float m = fmaxf(v0, v1);
    #pragma unroll
    for (int o = 16; o; o >>= 1) m = fmaxf(m, __shfl_xor_sync(0xffffffffu, m, o));
    float s = expf(v0 - m) + expf(v1 - m);
    #pragma unroll
    for (int o = 16; o; o >>= 1) s += __shfl_xor_sync(0xffffffffu, s, o);
    float ls = logf(s);
    g_lp[row * CC + lane]      = (v0 - m) - ls;
    g_lp[row * CC + lane + 32] = (v1 - m) - ls;
}

// branch-free sorted-descending 2-slot insert
#define INS2BF(A,B,KEY) do { u64 _k = (KEY);                               \
    u64 _mx = (_k > (A)) ? _k : (A);                                       \
    u64 _mn = (_k > (A)) ? (A) : _k;                                       \
    (A) = _mx;                                                             \
    (B) = (_mn > (B)) ? _mn : (B);                                         \
} while (0)

// ---------------------------------------------------------------------------
// One warp per batch element.
// ---------------------------------------------------------------------------
__global__ __launch_bounds__(32) void ctc_beam_kernel(
    const int* __restrict__ dlen, float* __restrict__ out)
{
    __shared__ float p_b[BEAM], p_nb[BEAM], tot[BEAM];
    __shared__ float stay_pb[BEAM], stay_pnb[BEAM];
    __shared__ u64   hcomb[BEAM], pphash[BEAM], cmask_s[BEAM];
    __shared__ int   lens[BEAM], lastc[BEAM], curn[BEAM];
    __shared__ float4 rec[BEAM];        // (tot, p_b, lastc-as-float, 0)
    __shared__ float lp_s[CC];
    __shared__ int   nodes[TT * BEAM];
    __shared__ int   order_s[TOPK];

    const unsigned FULL = 0xffffffffu;
    int b = blockIdx.x;
    int lane = threadIdx.x;

    if (lane < BEAM) {
        float pb = (lane == 0) ? 0.0f : NEGV;
        p_b[lane] = pb; p_nb[lane] = NEGV; tot[lane] = laexp(pb, NEGV);
        hcomb[lane] = 0ull; pphash[lane] = 0ull;
        lens[lane] = 0; lastc[lane] = -1; curn[lane] = -1;
    }
    unsigned actm = 1u;      // active-beam bitmask
    unsigned lenm = 0u;      // lens>0 bitmask
    int length = dlen[b]; if (length > TT) length = TT;

    float lpr0 = g_lp[b * CC + lane];
    float lpr1 = g_lp[b * CC + lane + 32];
    __syncwarp();

    for (int t = 0; t < length; ++t) {
        lp_s[lane] = lpr0; lp_s[lane + 32] = lpr1;
        __syncwarp();

        // ==== phase A: merge+stays+rec (lanes 0-15) | cmask (lanes 16-31) ====
        float stv = 0.0f;
        if (lane < BEAM) {
            int j = lane;
            int lj = lastc[j];
            int ljs = lj < 0 ? 0 : lj;
            u64 pp = pphash[j];
            float tj = tot[j], pbj = p_b[j];
            rec[j] = make_float4(tj, pbj, __int_as_float(lj), 0.0f);
            float spb = tj + lp_s[0];
            float lplj = lp_s[ljs];
            bool haslen = (lenm >> j) & 1;
            float spnb = haslen ? (p_nb[j] + lplj) : NEGV;
            unsigned mask = 0;
            #pragma unroll
            for (int i = 0; i < BEAM; ++i)
                mask |= (hcomb[i] == pp) ? (1u << i) : 0u;
            bool validj = ((actm >> j) & 1) && haslen;
            float merged = NEGV;   // == NEGV + log(1024) after f32 rounding
            if (validj && mask) {
                int cnt = __popc(mask);
                float mx = NEGV;
                unsigned mm = mask;
                while (mm) {
                    int i = __ffs(mm) - 1; mm &= mm - 1;
                    float ev = ((actm >> i) & 1)
                             ? (((lj == lastc[i]) ? p_b[i] : tot[i]) + lplj)
                             : NEGV;
                    mx = fmaxf(mx, ev);
                }
                float s = 0.0f; mm = mask;
                while (mm) {
                    int i = __ffs(mm) - 1; mm &= mm - 1;
                    float ev = ((actm >> i) & 1)
                             ? (((lj == lastc[i]) ? p_b[i] : tot[i]) + lplj)
                             : NEGV;
                    s += expf(ev - mx);
                }
                s += (float)(1024 - cnt) * expf(NEGV - mx);
                merged = mx + logf(s);
            }
            spnb = laexp(spnb, merged);
            stay_pb[j] = spb; stay_pnb[j] = spnb;
            stv = laexp(spb, spnb);
        } else {
            int i = lane - BEAM;
            u64 hci = hcomb[i];
            u64 cm = 1ull;                           // blank always masked
            unsigned mk = 0;
            #pragma unroll
            for (int j = 0; j < BEAM; ++j)
                mk |= (pphash[j] == hci) ? (1u << j) : 0u;
            mk &= actm & lenm;
            while (mk) {
                int j = __ffs(mk) - 1; mk &= mk - 1;
                cm |= 1ull << lastc[j];
            }
            if (!((actm >> i) & 1)) cm = ~0ull;      // inactive: mask all
            cmask_s[i] = cm;
        }
        __syncwarp();

        // ==== T0 = min stay_tot (prune threshold) ============================
        unsigned t0o = (lane < BEAM) ? f2ord(stv) : 0xffffffffu;
        t0o = __reduce_min_sync(FULL, t0o);
        float T0 = ord2f(t0o);

        // ==== phase B: branch-free pruned keys -> two 2-deep chains ==========
        u64 sk = (lane < BEAM)
               ? (((u64)f2ord(stv) << 32) | (unsigned)(((2047 - lane) << 6) | 0))
               : 0ull;
        u64 c0 = sk, c1 = 0ull, c2 = 0ull;
        u64 d0 = 0ull, d1 = 0ull;
        int nsv = (lane < BEAM) ? 1 : 0;
        #pragma unroll
        for (int i = 0; i < BEAM; ++i) {
            float4 r = rec[i];
            u64 cm = cmask_s[i];
            int li = __float_as_int(r.z);
            int ca = (lane + i) & 31, cb = ca + 32;   // per-beam rotation
            float va = ((ca == li) ? r.y : r.x) + lp_s[ca];
            float vb = ((cb == li) ? r.y : r.x) + lp_s[cb];
            bool ka = !((cm >> ca) & 1ull) && (va > T0);
            bool kb = !((cm >> cb) & 1ull) && (vb > T0);
            int ea = BEAM + i * CC + ca;
            int eb = BEAM + i * CC + cb;
            u64 keya = ka ? (((u64)f2ord(va) << 32)
                             | (unsigned)(((2047 - ea) << 6) | (1 + 2 * i))) : 0ull;
            u64 keyb = kb ? (((u64)f2ord(vb) << 32)
                             | (unsigned)(((2047 - eb) << 6) | (2 + 2 * i))) : 0ull;
            nsv += (int)ka + (int)kb;
            INS2BF(c0, c1, keya);
            INS2BF(d0, d1, keyb);
        }
        // merge sorted pairs (c0>=c1) and (d0>=d1) into sorted top-3 c0,c1,c2
        {
            u64 x  = (c0 > d0) ? d0 : c0;     // min(c0,d0)
            c0     = (c0 > d0) ? c0 : d0;     // max
            u64 y  = (c1 > d1) ? c1 : d1;     // max(c1,d1)
            u64 z  = (c1 > d1) ? d1 : c1;     // min(c1,d1)
            c1     = (x > y) ? x : y;
            u64 m2 = (x > y) ? y : x;
            c2     = (m2 > z) ? m2 : z;
        }
        int rem = nsv;

        // prefetch next lp row (hidden behind extraction)
        float lpn0, lpn1;
        {
            int nr = t + 1; if (nr > TT - 1) nr = TT - 1;
            lpn0 = g_lp[(nr * BB + b) * CC + lane];
            lpn1 = g_lp[(nr * BB + b) * CC + lane + 32];
        }

        // ==== phase C: top-16; 2 redux + branch-free pop; refill recomputes ==
        u64 sel_key = 0ull;
        u64 pmask = 0ull;
        #pragma unroll 1
        for (int k = 0; k < BEAM; ++k) {
            unsigned up = (unsigned)(c0 >> 32);
            unsigned um = __reduce_max_sync(FULL, up);
            unsigned lo = (up == um) ? (unsigned)c0 : 0u;
            unsigned lw = __reduce_max_sync(FULL, lo);
            u64 key = ((u64)um << 32) | lw;           // winner known to all
            sel_key = (lane == k) ? key : sel_key;
            bool win = (c0 == key);
            pmask |= win ? (1ull << (lw & 63u)) : 0ull;
            c0 = win ? c1 : c0;
            c1 = win ? c2 : c1;
            c2 = win ? 0ull : c2;
            rem -= (int)win;
            if (win && c0 == 0ull && rem > 0) {       // rare: recompute refill
                u64 e0 = 0ull, e1 = 0ull, e2 = 0ull;
                u64 f0 = 0ull, f1 = 0ull;
                if (!(pmask & 1ull)) e0 = sk;
                #pragma unroll
                for (int i = 0; i < BEAM; ++i) {
                    float4 r = rec[i];
                    u64 cm = cmask_s[i];
                    int li = __float_as_int(r.z);
                    int ca = (lane + i) & 31, cb = ca + 32;
                    float va = ((ca == li) ? r.y : r.x) + lp_s[ca];
                    float vb = ((cb == li) ? r.y : r.x) + lp_s[cb];
                    bool ka = !((cm >> ca) & 1ull) && (va > T0)
                              && !((pmask >> (1 + 2 * i)) & 1ull);
                    bool kb = !((cm >> cb) & 1ull) && (vb > T0)
                              && !((pmask >> (2 + 2 * i)) & 1ull);
                    int ea = BEAM + i * CC + ca;
                    int eb = BEAM + i * CC + cb;
                    u64 keya = ka ? (((u64)f2ord(va) << 32)
                                     | (unsigned)(((2047 - ea) << 6) | (1 + 2 * i))) : 0ull;
                    u64 keyb = kb ? (((u64)f2ord(vb) << 32)
                                     | (unsigned)(((2047 - eb) << 6) | (2 + 2 * i))) : 0ull;
                    INS2BF(e0, e1, keya);
                    INS2BF(f0, f1, keyb);
                }
                u64 x  = (e0 > f0) ? f0 : e0;
                e0     = (e0 > f0) ? e0 : f0;
                u64 y  = (e1 > f1) ? e1 : f1;
                u64 z  = (e1 > f1) ? f1 : e1;
                e1     = (x > y) ? x : y;
                u64 m2 = (x > y) ? y : x;
                e2     = (m2 > z) ? m2 : z;
                c0 = e0; c1 = e1; c2 = e2;
            }
        }
        __syncwarp();

        // ==== phase D: commit new beam state =================================
        float npb = 0.f, npnb = 0.f; u64 nh = 0ull, npp = 0ull;
        int nlen = 0, nlast = 0, ncur = 0, nodeval = 0, nact = 0;
        bool isext = false;
        if (lane < BEAM) {
            unsigned klo = (unsigned)sel_key;
            int idx = 2047 - (int)((klo >> 6) & 0x7ffu);
            float val = ord2f((unsigned)(sel_key >> 32));
            bool st = idx < BEAM;
            int parent = st ? idx : ((idx - BEAM) >> 6);
            int cnew   = st ? 0   : ((idx - BEAM) & 63);
            npb  = st ? stay_pb[parent]  : NEGV;
            npnb = st ? stay_pnb[parent] : val;
            u64 hp = hcomb[parent];
            unsigned ph1 = (unsigned)(hp >> 32), ph2 = (unsigned)hp;
            unsigned cc1 = (unsigned)cnew + 1u;
            nh  = st ? hp : (((u64)(ph1 * 1000003u + cc1) << 32) | (ph2 * 69069u + cc1));
            npp = st ? pphash[parent] : hp;
            nlen  = lens[parent] + (st ? 0 : 1);
            nlast = st ? lastc[parent] : cnew;
            int pcur = curn[parent];
            ncur  = st ? pcur : (t * BEAM + lane);
            isext = !st;
            nodeval = ((pcur + 1) << 6) | cnew;
            nact = (val > -5e8f) ? 1 : 0;
        }
        __syncwarp();
        if (lane < BEAM) {
            p_b[lane] = npb; p_nb[lane] = npnb; tot[lane] = laexp(npb, npnb);
            hcomb[lane] = nh; pphash[lane] = npp;
            lens[lane] = nlen; lastc[lane] = nlast; curn[lane] = ncur;
            if (isext) nodes[t * BEAM + lane] = nodeval;
        }
        actm = __ballot_sync(FULL, nact) & 0xffffu;
        lenm = __ballot_sync(FULL, nlen > 0) & 0xffffu;
        lpr0 = lpn0; lpr1 = lpn1;
        __syncwarp();
    }

    // ==== final top-4 + outputs ==============================================
    for (int e = lane; e < TOPK * TT; e += 32)
        out[2 * BB * TOPK + b * TOPK * TT + e] = -1.0f;
    __syncwarp();

    if (lane == 0) {
        unsigned used = 0u;
        for (int k = 0; k < TOPK; ++k) {
            float bv = -FLT_MAX; int bi = 0;
            for (int i = 0; i < BEAM; ++i) {
                if ((used >> i) & 1u) continue;
                if (tot[i] > bv) { bv = tot[i]; bi = i; }
            }
            used |= 1u << bi;
            order_s[k] = bi;
            out[b * TOPK + k]             = -bv;
            out[BB * TOPK + b * TOPK + k] = (float)lens[bi];
        }
    }
    __syncwarp();

    if (lane < TOPK) {
        int bm = order_s[lane];
        int id = curn[bm];
        float* lbl = out + 2 * BB * TOPK + (b * TOPK + lane) * TT;
        for (int pos = lens[bm] - 1; pos >= 0; --pos) {
            int pk = nodes[id];
            lbl[pos] = (float)(pk & 63);
            id = (pk >> 6) - 1;
        }
    }
}

extern "C" void kernel_launch(void* const* d_in, const int* in_sizes, int n_in,
                              void* d_out, int out_size)
{
    const float* data = (const float*)d_in[0];
    const int*   dlen = (const int*)d_in[1];
    float*       out  = (float*)d_out;

    logsoftmax_kernel<<<(TT * BB) / 8, 256>>>(data);
    ctc_beam_kernel<<<BB, 32>>>(dlen, out);
}

// round 17
// speedup vs baseline: 1.1709x; 1.1709x over previous
#include <cuda_runtime.h>
#include <math.h>
#include <float.h>

#define TT 256
#define BB 32
#define CC 64
#define BEAM 16
#define TOPK 4
#define NEGV (-1e9f)

typedef unsigned long long u64;

__device__ float g_lp[TT * BB * CC];

__device__ __forceinline__ float laexp(float a, float b) {
    return fmaxf(a, b) + log1pf(expf(-fabsf(a - b)));
}
__device__ __forceinline__ unsigned f2ord(float v) {
    unsigned u = __float_as_uint(v);
    return u ^ (unsigned)(((int)u >> 31) | 0x80000000);
}
__device__ __forceinline__ float ord2f(unsigned o) {
    unsigned u = (o & 0x80000000u) ? (o ^ 0x80000000u) : ~o;
    return __uint_as_float(u);
}

// ---------------------------------------------------------------------------
__global__ void logsoftmax_kernel(const float* __restrict__ data) {
    int row  = blockIdx.x * 8 + (threadIdx.x >> 5);
    int lane = threadIdx.x & 31;
    if (row >= TT * BB) return;
    const float* x = data + row * CC;
    float v0 = x[lane], v1 = x[lane + 32];
    float m = fmaxf(v0, v1);
    #pragma unroll
    for (int o = 16; o; o >>= 1) m = fmaxf(m, __shfl_xor_sync(0xffffffffu, m, o));
    float s = expf(v0 - m) + expf(v1 - m);
    #pragma unroll
    for (int o = 16; o; o >>= 1) s += __shfl_xor_sync(0xffffffffu, s, o);
    float ls = logf(s);
    g_lp[row * CC + lane]      = (v0 - m) - ls;
    g_lp[row * CC + lane + 32] = (v1 - m) - ls;
}

// branch-free sorted-descending 3-slot insert (SEL networks, no branches)
#define INS3BF(A,B,Cv,KEY) do { u64 _k = (KEY);                            \
    u64 _mx0 = (_k > (A)) ? _k : (A);                                      \
    u64 _mn0 = (_k > (A)) ? (A) : _k;                                      \
    (A) = _mx0;                                                            \
    u64 _mx1 = (_mn0 > (B)) ? _mn0 : (B);                                  \
    u64 _mn1 = (_mn0 > (B)) ? (B) : _mn0;                                  \
    (B) = _mx1;                                                            \
    (Cv) = (_mn1 > (Cv)) ? _mn1 : (Cv);                                    \
} while (0)

// ---------------------------------------------------------------------------
// One warp per batch element.
// ---------------------------------------------------------------------------
__global__ __launch_bounds__(32) void ctc_beam_kernel(
    const int* __restrict__ dlen, float* __restrict__ out)
{
    __shared__ float p_b[BEAM], p_nb[BEAM], tot[BEAM];
    __shared__ float stay_pb[BEAM], stay_pnb[BEAM];
    __shared__ u64   hcomb[BEAM], pphash[BEAM], cmask_s[BEAM];
    __shared__ int   lens[BEAM], lastc[BEAM], curn[BEAM];
    __shared__ float4 rec[BEAM];        // (tot, p_b, lastc-as-float, 0)
    __shared__ u64   kk_sh[33 * 32];    // survivor keys, [slot*32 + lane]
    __shared__ int   nodes[TT * BEAM];
    __shared__ int   order_s[TOPK];

    const unsigned FULL = 0xffffffffu;
    int b = blockIdx.x;
    int lane = threadIdx.x;

    if (lane < BEAM) {
        float pb = (lane == 0) ? 0.0f : NEGV;
        p_b[lane] = pb; p_nb[lane] = NEGV; tot[lane] = laexp(pb, NEGV);
        hcomb[lane] = 0ull; pphash[lane] = 0ull;
        lens[lane] = 0; lastc[lane] = -1; curn[lane] = -1;
    }
    unsigned actm = 1u;      // active-beam bitmask
    unsigned lenm = 0u;      // lens>0 bitmask
    int length = dlen[b]; if (length > TT) length = TT;

    float lpr0 = g_lp[b * CC + lane];
    float lpr1 = g_lp[b * CC + lane + 32];
    __syncwarp();

    for (int t = 0; t < length; ++t) {
        // pre-branch lp broadcasts (must be warp-uniform execution)
        int lj_all  = lastc[lane & 15];
        int ljs_all = lj_all < 0 ? 0 : lj_all;
        float lpA = __shfl_sync(FULL, lpr0, ljs_all);
        float lpB = __shfl_sync(FULL, lpr1, ljs_all);
        float lplj = (ljs_all < 32) ? lpA : lpB;
        float lp0  = __shfl_sync(FULL, lpr0, 0);

        // ==== phase A: merge+stays+rec (lanes 0-15) | cmask (lanes 16-31) ====
        float stv = 0.0f;
        if (lane < BEAM) {
            int j = lane;
            int lj = lj_all;
            u64 pp = pphash[j];
            float tj = tot[j], pbj = p_b[j];
            rec[j] = make_float4(tj, pbj, __int_as_float(lj), 0.0f);
            float spb = tj + lp0;
            bool haslen = (lenm >> j) & 1;
            float spnb = haslen ? (p_nb[j] + lplj) : NEGV;
            unsigned mask = 0;
            #pragma unroll
            for (int i = 0; i < BEAM; ++i)
                mask |= (hcomb[i] == pp) ? (1u << i) : 0u;
            bool validj = ((actm >> j) & 1) && haslen;
            float merged = NEGV;   // == NEGV + log(1024) after f32 rounding
            if (validj && mask) {
                int cnt = __popc(mask);
                float mx = NEGV;
                unsigned mm = mask;
                while (mm) {
                    int i = __ffs(mm) - 1; mm &= mm - 1;
                    float ev = ((actm >> i) & 1)
                             ? (((lj == lastc[i]) ? p_b[i] : tot[i]) + lplj)
                             : NEGV;
                    mx = fmaxf(mx, ev);
                }
                float s = 0.0f; mm = mask;
                while (mm) {
                    int i = __ffs(mm) - 1; mm &= mm - 1;
                    float ev = ((actm >> i) & 1)
                             ? (((lj == lastc[i]) ? p_b[i] : tot[i]) + lplj)
                             : NEGV;
                    s += expf(ev - mx);
                }
                s += (float)(1024 - cnt) * expf(NEGV - mx);
                merged = mx + logf(s);
            }
            spnb = laexp(spnb, merged);
            stay_pb[j] = spb; stay_pnb[j] = spnb;
            stv = laexp(spb, spnb);
        } else {
            int i = lane - BEAM;
            u64 hci = hcomb[i];
            u64 cm = 1ull;                           // blank always masked
            unsigned mk = 0;
            #pragma unroll
            for (int j = 0; j < BEAM; ++j)
                mk |= (pphash[j] == hci) ? (1u << j) : 0u;
            mk &= actm & lenm;
            while (mk) {
                int j = __ffs(mk) - 1; mk &= mk - 1;
                cm |= 1ull << lastc[j];
            }
            if (!((actm >> i) & 1)) cm = ~0ull;      // inactive: mask all
            cmask_s[i] = cm;
        }
        __syncwarp();

        // ==== T0 = min stay_tot (prune threshold) ============================
        unsigned t0o = (lane < BEAM) ? f2ord(stv) : 0xffffffffu;
        t0o = __reduce_min_sync(FULL, t0o);
        float T0 = ord2f(t0o);

        // ==== phase B: branch-free pruned keys -> fixed slots + 3-cache ======
        u64 c0 = 0ull, c1 = 0ull, c2 = 0ull;
        u64 d0 = 0ull, d1 = 0ull, d2 = 0ull;
        u64 sk = (lane < BEAM)
               ? (((u64)f2ord(stv) << 32) | (unsigned)(((2047 - lane) << 6) | 0))
               : 0ull;
        kk_sh[lane] = sk;
        c0 = sk;
        int nsv = (lane < BEAM) ? 1 : 0;
        #pragma unroll
        for (int i = 0; i < BEAM; ++i) {
            float4 r = rec[i];
            u64 cm = cmask_s[i];
            int li = __float_as_int(r.z);
            int ca = (lane + i) & 31, cb = ca + 32;   // per-beam rotation
            float lpa = __shfl_sync(FULL, lpr0, lane + i);
            float lpb = __shfl_sync(FULL, lpr1, lane + i);
            float va = ((ca == li) ? r.y : r.x) + lpa;
            float vb = ((cb == li) ? r.y : r.x) + lpb;
            bool ka = !((cm >> ca) & 1ull) && (va > T0);
            bool kb = !((cm >> cb) & 1ull) && (vb > T0);
            int ea = BEAM + i * CC + ca;
            int eb = BEAM + i * CC + cb;
            u64 keya = ka ? (((u64)f2ord(va) << 32)
                             | (unsigned)(((2047 - ea) << 6) | (1 + 2 * i))) : 0ull;
            u64 keyb = kb ? (((u64)f2ord(vb) << 32)
                             | (unsigned)(((2047 - eb) << 6) | (2 + 2 * i))) : 0ull;
            kk_sh[(1 + 2 * i) * 32 + lane] = keya;
            kk_sh[(2 + 2 * i) * 32 + lane] = keyb;
            nsv += (int)ka + (int)kb;
            INS3BF(c0, c1, c2, keya);
            INS3BF(d0, d1, d2, keyb);
        }
        INS3BF(c0, c1, c2, d0); INS3BF(c0, c1, c2, d1); INS3BF(c0, c1, c2, d2);
        int rem = nsv;

        // prefetch next lp row (hidden behind extraction)
        float lpn0, lpn1;
        {
            int nr = t + 1; if (nr > TT - 1) nr = TT - 1;
            lpn0 = g_lp[(nr * BB + b) * CC + lane];
            lpn1 = g_lp[(nr * BB + b) * CC + lane + 32];
        }

        // ==== phase C: top-16; 2 redux + branch-free pop per round ===========
        u64 sel_key = 0ull;
        u64 pmask = 0ull;
        #pragma unroll 1
        for (int k = 0; k < BEAM; ++k) {
            unsigned up = (unsigned)(c0 >> 32);
            unsigned um = __reduce_max_sync(FULL, up);
            unsigned lo = (up == um) ? (unsigned)c0 : 0u;
            unsigned lw = __reduce_max_sync(FULL, lo);
            u64 key = ((u64)um << 32) | lw;           // winner known to all
            sel_key = (lane == k) ? key : sel_key;
            bool win = (c0 == key);
            pmask |= win ? (1ull << (lw & 63u)) : 0ull;
            c0 = win ? c1 : c0;
            c1 = win ? c2 : c1;
            c2 = win ? 0ull : c2;
            rem -= (int)win;
            if (win && c0 == 0ull && rem > 0) {       // rare refill, fixed slots
                #pragma unroll 1
                for (int j2 = 0; j2 < 33; ++j2) {
                    u64 kx = ((pmask >> j2) & 1ull) ? 0ull : kk_sh[j2 * 32 + lane];
                    INS3BF(c0, c1, c2, kx);
                }
            }
        }
        __syncwarp();

        // ==== phase D: all lanes compute; predicated commit ==================
        {
            unsigned klo = (unsigned)sel_key;
            int idx = 2047 - (int)((klo >> 6) & 0x7ffu);
            float val = ord2f((unsigned)(sel_key >> 32));
            bool st = idx < BEAM;
            int parent = (st ? idx : ((idx - BEAM) >> 6)) & 15;
            int cnew   = st ? 0   : ((idx - BEAM) & 63);
            float npb  = st ? stay_pb[parent]  : NEGV;
            float npnb = st ? stay_pnb[parent] : val;
            u64 hp = hcomb[parent];
            unsigned ph1 = (unsigned)(hp >> 32), ph2 = (unsigned)hp;
            unsigned cc1 = (unsigned)cnew + 1u;
            u64 nh  = st ? hp : (((u64)(ph1 * 1000003u + cc1) << 32) | (ph2 * 69069u + cc1));
            u64 npp = st ? pphash[parent] : hp;
            int nlen  = lens[parent] + (st ? 0 : 1);
            int nlast = st ? lastc[parent] : cnew;
            int pcur  = curn[parent];
            int ncur  = st ? pcur : (t * BEAM + lane);
            int nodeval = ((pcur + 1) << 6) | cnew;
            int nact = (val > -5e8f) ? 1 : 0;   // NaN (lanes>=16) -> 0
            float ntot = laexp(npb, npnb);
            __syncwarp();
            if (lane < BEAM) {
                p_b[lane] = npb; p_nb[lane] = npnb; tot[lane] = ntot;
                hcomb[lane] = nh; pphash[lane] = npp;
                lens[lane] = nlen; lastc[lane] = nlast; curn[lane] = ncur;
                nodes[t * BEAM + lane] = nodeval;   // unreferenced unless ncur points here
            }
            actm = __ballot_sync(FULL, nact) & 0xffffu;
            lenm = __ballot_sync(FULL, nlen > 0) & 0xffffu;
        }
        lpr0 = lpn0; lpr1 = lpn1;
        __syncwarp();
    }

    // ==== final top-4 + outputs ==============================================
    for (int e = lane; e < TOPK * TT; e += 32)
        out[2 * BB * TOPK + b * TOPK * TT + e] = -1.0f;
    __syncwarp();

    if (lane == 0) {
        unsigned used = 0u;
        for (int k = 0; k < TOPK; ++k) {
            float bv = -FLT_MAX; int bi = 0;
            for (int i = 0; i < BEAM; ++i) {
                if ((used >> i) & 1u) continue;
                if (tot[i] > bv) { bv = tot[i]; bi = i; }
            }
            used |= 1u << bi;
            order_s[k] = bi;
            out[b * TOPK + k]             = -bv;
            out[BB * TOPK + b * TOPK + k] = (float)lens[bi];
        }
    }
    __syncwarp();

    if (lane < TOPK) {
        int bm = order_s[lane];
        int id = curn[bm];
        float* lbl = out + 2 * BB * TOPK + (b * TOPK + lane) * TT;
        for (int pos = lens[bm] - 1; pos >= 0; --pos) {
            int pk = nodes[id];
            lbl[pos] = (float)(pk & 63);
            id = (pk >> 6) - 1;
        }
    }
}

extern "C" void kernel_launch(void* const* d_in, const int* in_sizes, int n_in,
                              void* d_out, int out_size)
{
    const float* data = (const float*)d_in[0];
    const int*   dlen = (const int*)d_in[1];
    float*       out  = (float*)d_out;

    logsoftmax_kernel<<<(TT * BB) / 8, 256>>>(data);
    ctc_beam_kernel<<<BB, 32>>>(dlen, out);
}